// round 1
// baseline (speedup 1.0000x reference)
#include <cuda_runtime.h>

// Problem constants (fixed for this problem instance)
#define FP          80          // frame period
#define MTAPS       24          // FIR taps (lags 1..24)
#define NSTAGES     20          // taylor_order
#define BATCH       8
#define NFRAMES     1024
#define TLEN        (NFRAMES * FP)   // 81920

// Kernel tiling
#define RPT         4                 // t's per thread (4 | 80 -> never crosses frame)
#define BLOCK       512
#define WINW        (BLOCK * RPT)     // 2048 values per block window
#define HALO        (NSTAGES * MTAPS) // 480
#define TBOUT       (WINW - HALO)     // 1568 useful outputs per block
#define PADZ        24                // zero pad at window front (implicit x[t<0]=0)
#define BPB         ((TLEN + TBOUT - 1) / TBOUT)   // 53 blocks per batch

__global__ void __launch_bounds__(BLOCK, 1)
fir_taylor_kernel(const float* __restrict__ x,
                  const float* __restrict__ mc,
                  const float* __restrict__ a,
                  const float* __restrict__ wts,
                  float* __restrict__ out)
{
    __shared__ float buf0[WINW + PADZ];
    __shared__ float buf1[WINW + PADZ];
    __shared__ float s_a[NSTAGES + 1];
    __shared__ float s_w[NSTAGES + 1];

    const int tid = threadIdx.x;
    const int blk = blockIdx.x;
    const int b   = blk / BPB;
    const int tb  = blk % BPB;
    const int t0  = tb * TBOUT;       // global start of this block's output region
    const int g0  = t0 - HALO;        // global t corresponding to local position 0

    if (tid <= NSTAGES) { s_a[tid] = a[tid]; s_w[tid] = wts[tid]; }
    if (tid < PADZ)     { buf0[tid] = 0.0f; buf1[tid] = 0.0f; }

    // Load x window (zero outside [0, TLEN))
    const float* xb = x + b * TLEN;
    for (int p = tid; p < WINW; p += BLOCK) {
        int t = g0 + p;
        buf0[PADZ + p] = (t >= 0 && t < TLEN) ? xb[t] : 0.0f;
    }

    // ---- per-thread coefficient setup (registers) ----
    const int lp    = tid * RPT;          // local position of first owned t
    const int tbase = g0 + lp;            // global t of first owned t
    int tc = tbase < 0 ? 0 : (tbase >= TLEN ? TLEN - 1 : tbase);
    int n  = tc / FP;
    int n1 = (n + 1 < NFRAMES) ? n + 1 : NFRAMES - 1;
    const float invP = 1.0f / (float)FP;
    float w0 = (float)(tc - n * FP) * invP;

    const float* mrow0 = mc + ((long)b * NFRAMES + n)  * (MTAPS + 1);
    const float* mrow1 = mc + ((long)b * NFRAMES + n1) * (MTAPS + 1);

    float cc[MTAPS], dd[MTAPS];
#pragma unroll
    for (int j = 0; j < MTAPS; j++) {
        float c0v = mrow0[j + 1];
        float c1v = mrow1[j + 1];
        dd[j] = c1v - c0v;
        cc[j] = fmaf(w0, dd[j], c0v);    // coefficient at r = 0
    }
    const float k0 = mrow0[0];
    const float dk = mrow1[0] - k0;

    __syncthreads();

    // y accumulators: y = x * a[0]
    float y[RPT];
#pragma unroll
    for (int r = 0; r < RPT; r++) y[r] = buf0[PADZ + lp + r] * s_a[0];

    float* cur = buf0;
    float* nxt = buf1;

    for (int i = 1; i <= NSTAGES; i++) {
        const float wgt = s_w[i];
        const float ai  = s_a[i];

        // window cur[t-24 .. t+3]  (28 floats, float4 aligned: PADZ+lp-24 = tid*4)
        float win[RPT + MTAPS];
        const float4* v = (const float4*)(cur + PADZ + lp - MTAPS);
#pragma unroll
        for (int q = 0; q < (RPT + MTAPS) / 4; q++) {
            float4 f = v[q];
            win[4*q + 0] = f.x; win[4*q + 1] = f.y;
            win[4*q + 2] = f.z; win[4*q + 3] = f.w;
        }

        float acc[RPT];
#pragma unroll
        for (int r = 0; r < RPT; r++) {
            const float wr = (float)r * invP;   // coef(t+r) = cc + wr*dd
            float s = 0.0f;
#pragma unroll
            for (int j = 1; j <= MTAPS; j++) {
                float coef = fmaf(wr, dd[j - 1], cc[j - 1]);
                s = fmaf(win[MTAPS + r - j], coef, s);
            }
            acc[r] = s * wgt;
            y[r]   = fmaf(acc[r], ai, y[r]);
        }

        float4 st; st.x = acc[0]; st.y = acc[1]; st.z = acc[2]; st.w = acc[3];
        *((float4*)(nxt + PADZ + lp)) = st;
        __syncthreads();
        float* tmp = cur; cur = nxt; nxt = tmp;
    }

    // ---- epilogue: out = y * exp(interp(mc[...,0])) for the exact region ----
    if (lp >= HALO) {
        float* ob = out + b * TLEN;
#pragma unroll
        for (int r = 0; r < RPT; r++) {
            int tt = tbase + r;
            if (tt < TLEN) {
                float K = expf(fmaf(w0 + (float)r * invP, dk, k0));
                ob[tt] = y[r] * K;
            }
        }
    }
}

extern "C" void kernel_launch(void* const* d_in, const int* in_sizes, int n_in,
                              void* d_out, int out_size)
{
    (void)in_sizes; (void)n_in; (void)out_size;
    const float* x   = (const float*)d_in[0];
    const float* mc  = (const float*)d_in[1];
    const float* a   = (const float*)d_in[2];
    const float* wts = (const float*)d_in[3];
    float* out = (float*)d_out;

    dim3 grid(BATCH * BPB);
    dim3 blockDim3(BLOCK);
    fir_taylor_kernel<<<grid, blockDim3>>>(x, mc, a, wts, out);
}